// round 13
// baseline (speedup 1.0000x reference)
#include <cuda_runtime.h>
#include <cuda_fp16.h>
#include <math.h>
#include <stdint.h>

#define BB 2
#define TT 2048
#define DD 1024
#define HH 16
#define HD 64
#define MM (BB*TT)

// ---------------- scratch ----------------
__device__ __half g_xh[(size_t)MM*DD];
__device__ __half g_qh[(size_t)MM*DD];
__device__ __half g_kh[(size_t)MM*DD];
__device__ __half g_vh[(size_t)MM*DD];
__device__ __half g_ah[(size_t)MM*DD];
__device__ __half g_wh[4*(size_t)DD*DD];

// ---------------- helpers ----------------
__device__ __forceinline__ uint32_t smem_u32(const void* p) {
    uint32_t a;
    asm("{ .reg .u64 t; cvta.to.shared.u64 t, %1; cvt.u32.u64 %0, t; }" : "=r"(a) : "l"(p));
    return a;
}
__device__ __forceinline__ float fast_exp2(float x) {
    float y; asm("ex2.approx.ftz.f32 %0, %1;" : "=f"(y) : "f"(x)); return y;
}
__device__ __forceinline__ void mma_f16(float* c, const uint32_t* a, uint32_t b0, uint32_t b1) {
    asm("mma.sync.aligned.m16n8k16.row.col.f32.f16.f16.f32 "
        "{%0,%1,%2,%3}, {%4,%5,%6,%7}, {%8,%9}, {%0,%1,%2,%3};"
        : "+f"(c[0]), "+f"(c[1]), "+f"(c[2]), "+f"(c[3])
        : "r"(a[0]), "r"(a[1]), "r"(a[2]), "r"(a[3]), "r"(b0), "r"(b1));
}
__device__ __forceinline__ void ldsm4(uint32_t addr, uint32_t* r) {
    asm volatile("ldmatrix.sync.aligned.m8n8.x4.shared.b16 {%0,%1,%2,%3}, [%4];"
        : "=r"(r[0]), "=r"(r[1]), "=r"(r[2]), "=r"(r[3]) : "r"(addr));
}
__device__ __forceinline__ void ldsm4t(uint32_t addr, uint32_t* r) {
    asm volatile("ldmatrix.sync.aligned.m8n8.x4.trans.shared.b16 {%0,%1,%2,%3}, [%4];"
        : "=r"(r[0]), "=r"(r[1]), "=r"(r[2]), "=r"(r[3]) : "r"(addr));
}
__device__ __forceinline__ void cpa(uint32_t dst, const void* src) {
    asm volatile("cp.async.ca.shared.global [%0], [%1], 16;" :: "r"(dst), "l"(src));
}
__device__ __forceinline__ void commitg() {
    asm volatile("cp.async.commit_group;" ::: "memory");
}
template<int N> __device__ __forceinline__ void waitg() {
    asm volatile("cp.async.wait_group %0;" :: "n"(N) : "memory");
}
__device__ __forceinline__ uint32_t pack2h(float x, float y) {
    uint32_t r; asm("cvt.rn.f16x2.f32 %0, %1, %2;" : "=r"(r) : "f"(y), "f"(x)); return r;
}

// ---------------------------------------------------------------------------
__global__ void tohalf(const float* __restrict__ in, __half* __restrict__ out)
{
    const int i = blockIdx.x * blockDim.x + threadIdx.x;
    float4 v = ((const float4*)in)[i];
    __half2* p = (__half2*)out;
    p[2*i]   = __floats2half2_rn(v.x, v.y);
    p[2*i+1] = __floats2half2_rn(v.z, v.w);
}

__global__ void transp4(const float* __restrict__ W0, const float* __restrict__ W1,
                        const float* __restrict__ W2, const float* __restrict__ W3,
                        __half* __restrict__ Bh)
{
    __shared__ float t[32][33];
    const int z = blockIdx.z;
    const float* A = (z == 0) ? W0 : (z == 1) ? W1 : (z == 2) ? W2 : W3;
    const size_t zo = (size_t)z * DD * DD;
    const int bx = blockIdx.x * 32, by = blockIdx.y * 32;
    const int x = threadIdx.x, y = threadIdx.y;
    #pragma unroll
    for (int i = 0; i < 32; i += 8)
        t[y + i][x] = A[(size_t)(by + y + i) * DD + bx + x];
    __syncthreads();
    #pragma unroll
    for (int i = 0; i < 32; i += 8)
        Bh[zo + (size_t)(bx + y + i) * DD + by + x] = __float2half_rn(t[x][y + i]);
}

// ---------------------------------------------------------------------------
// GEMM: plain fp16 mma.sync + ldmatrix + 3-stage cp.async pipeline (waitg<1>).
// MODE 0: fp32 out. MODE 1: merged QKV, single-fp16 scatter to (B,H,T,hd).
// ---------------------------------------------------------------------------
#define G_A  0
#define G_B  8192
#define G_STG 16384
#define GEMM_SMEM 49152
#define NIT (DD/32)

#define GEMM_LOAD(IT, STG) { \
    const int k0_ = (IT) * 32; \
    _Pragma("unroll") \
    for (int q_ = 0; q_ < 4; q_++) { \
        int idx_ = q_ * 256 + tid; \
        int buf_ = idx_ >> 9, wi_ = idx_ & 511; \
        int row_ = wi_ >> 2, kc_ = wi_ & 3; \
        uint32_t dst_ = sb + (STG)*G_STG + buf_*8192 + row_*64 + ((kc_ ^ ((row_>>1)&3)) << 4); \
        const __half* src_ = buf_ ? (Bh + (size_t)(n0 + row_)*DD + k0_ + kc_*8) \
                                  : (Ah + (size_t)(m0 + row_)*DD + k0_ + kc_*8); \
        cpa(dst_, src_); \
    } }

template<int MODE>
__global__ __launch_bounds__(256, 2)
void mma_gemm(const __half* __restrict__ Ah, const __half* __restrict__ Wh,
              const float* __restrict__ b0, const float* __restrict__ b1,
              const float* __restrict__ b2,
              float* __restrict__ outf,
              __half* __restrict__ oh0, __half* __restrict__ oh1, __half* __restrict__ oh2)
{
    extern __shared__ __align__(1024) char smem[];
    const uint32_t sb = smem_u32(smem);
    const int tid  = threadIdx.x;
    const int wid  = tid >> 5, lane = tid & 31;
    const int g    = lane >> 2, t4 = lane & 3;
    const int grp  = lane >> 3, wi = lane & 7;
    const int wm   = wid & 3,  wn = wid >> 2;
    const int m0   = blockIdx.y * 128, n0 = blockIdx.x * 128;
    const int z    = blockIdx.z;

    const size_t WSZ = (size_t)DD * DD;
    const __half* Bh = Wh + (size_t)z * WSZ;
    const float* bias = (z == 0) ? b0 : (z == 1) ? b1 : b2;
    __half* outh = (z == 0) ? oh0 : (z == 1) ? oh1 : oh2;

    float c[2][8][4];
    #pragma unroll
    for (int mb = 0; mb < 2; mb++)
        #pragma unroll
        for (int nb = 0; nb < 8; nb++)
            #pragma unroll
            for (int j = 0; j < 4; j++) c[mb][nb][j] = 0.f;

    GEMM_LOAD(0, 0); commitg();
    GEMM_LOAD(1, 1); commitg();

    int st = 0, st2 = 2;  // current compute stage; stage for it+2
    for (int it = 0; it < NIT; it++) {
        if (it + 1 < NIT) waitg<1>(); else waitg<0>();
        __syncthreads();
        if (it + 2 < NIT) { GEMM_LOAD(it+2, st2); commitg(); }
        const uint32_t base = sb + st * G_STG;
        st2 = st;
        st = (st + 1 == 3) ? 0 : st + 1;

        #pragma unroll
        for (int ks = 0; ks < 2; ks++) {
            uint32_t ah[2][4];
            #pragma unroll
            for (int mb = 0; mb < 2; mb++) {
                const int row = wm*32 + mb*16 + (grp & 1)*8 + wi;
                const int kb  = ks*32 + (grp >> 1)*16;
                const uint32_t off = row*64 + ((((kb >> 4) ^ ((row >> 1) & 3))) << 4);
                ldsm4(base + G_A + off, ah[mb]);
            }
            #pragma unroll
            for (int nbp = 0; nbp < 4; nbp++) {
                const int rowb = wn*64 + nbp*16 + (grp >> 1)*8 + wi;
                const int kb2  = ks*32 + (grp & 1)*16;
                const uint32_t offb = rowb*64 + ((((kb2 >> 4) ^ ((rowb >> 1) & 3))) << 4);
                uint32_t bh[4];
                ldsm4(base + G_B + offb, bh);
                #pragma unroll
                for (int mb = 0; mb < 2; mb++) {
                    mma_f16(c[mb][2*nbp],   ah[mb], bh[0], bh[1]);
                    mma_f16(c[mb][2*nbp+1], ah[mb], bh[2], bh[3]);
                }
            }
        }
    }

    #pragma unroll
    for (int mb = 0; mb < 2; mb++) {
        const int row = m0 + wm*32 + mb*16 + g;
        #pragma unroll
        for (int nb = 0; nb < 8; nb++) {
            const int col = n0 + wn*64 + nb*8 + t4*2;
            const float bx = bias[col], by = bias[col+1];
            const float v0x = c[mb][nb][0] + bx, v0y = c[mb][nb][1] + by;
            const float v1x = c[mb][nb][2] + bx, v1y = c[mb][nb][3] + by;
            if (MODE == 0) {
                *(float2*)(outf + (size_t)row * DD + col)       = make_float2(v0x, v0y);
                *(float2*)(outf + (size_t)(row + 8) * DD + col) = make_float2(v1x, v1y);
            } else {
                const int h = col >> 6, d = col & 63;
                const int b0r = row >> 11, t0 = row & (TT-1);
                const int b1r = (row+8) >> 11, t1 = (row+8) & (TT-1);
                const size_t o0 = (((size_t)(b0r*HH + h) * TT + t0) * HD) + d;
                const size_t o1 = (((size_t)(b1r*HH + h) * TT + t1) * HD) + d;
                *(__half2*)(outh + o0) = __floats2half2_rn(v0x, v0y);
                *(__half2*)(outh + o1) = __floats2half2_rn(v1x, v1y);
            }
        }
    }
}

// ---------------------------------------------------------------------------
// Flash attention (single fp16): 64-query tiles, 128 threads, 3 CTAs/SM,
// 3-stage KV cp.async pipeline (waitg<1>).
// SMEM 56KB: Q 8K + 3 stages x (K 8K + V 8K).
// ---------------------------------------------------------------------------
#define A_QH 0
#define A_ST(s) (8192 + (s)*16384)
#define ATT_SMEM 57344

#define KV_PREFETCH(KT, STG) { \
    _Pragma("unroll") \
    for (int q_ = 0; q_ < 8; q_++) { \
        int idx_ = q_ * 128 + tid; \
        int arr_ = idx_ >> 9, wi2_ = idx_ & 511; \
        int row_ = wi2_ >> 3, ch_ = wi2_ & 7; \
        uint32_t dst_ = sb + A_ST(STG) + arr_*8192 + row_*128 + ((ch_ ^ (row_ & 7)) << 4); \
        const __half* p_ = arr_ ? Vh : Kh; \
        cpa(dst_, p_ + bo + (size_t)((KT)*64 + row_)*HD + ch_*8); \
    } }

__global__ __launch_bounds__(128, 3)
void attn_mma(const __half* __restrict__ Qh,
              const __half* __restrict__ Kh, const __half* __restrict__ Vh,
              __half* __restrict__ Oh)
{
    extern __shared__ __align__(1024) char smem[];
    const uint32_t sb = smem_u32(smem);
    const int tid  = threadIdx.x, lane = tid & 31, warp = tid >> 5;
    const int g    = lane >> 2, t4 = lane & 3;
    const int grp  = lane >> 3, wi = lane & 7;
    const int qt   = (int)gridDim.x - 1 - (int)blockIdx.x;
    const int bh   = blockIdx.y, b = bh >> 4, h = bh & 15;
    const size_t bo = (size_t)bh * TT * HD;

    // group 0: Q tile + KV(0); group 1: KV(1) if present
    #pragma unroll
    for (int q = 0; q < 4; q++) {
        int idx = q * 128 + tid;
        int row = idx >> 3, ch = idx & 7;
        uint32_t dst = sb + A_QH + row*128 + ((ch ^ (row & 7)) << 4);
        cpa(dst, Qh + bo + (size_t)(qt*64 + row)*HD + ch*8);
    }
    KV_PREFETCH(0, 0); commitg();
    if (qt >= 1) { KV_PREFETCH(1, 1); commitg(); }

    const float LOG2E  = 1.4426950408889634f;
    const float scale2 = 0.125f * LOG2E;
    const float slope2 = exp2f(-0.5f * (float)(h + 1)) * LOG2E;

    float cO[8][4];
    #pragma unroll
    for (int nb = 0; nb < 8; nb++)
        #pragma unroll
        for (int j = 0; j < 4; j++) cO[nb][j] = 0.f;
    float mr0 = -1e30f, mr1 = -1e30f, lr0 = 0.f, lr1 = 0.f;
    uint32_t qfh[4][4];

    int st = 0, st2 = 2;
    for (int kt = 0; kt <= qt; kt++) {
        if (kt < qt) waitg<1>(); else waitg<0>();
        __syncthreads();
        if (kt + 2 <= qt) { KV_PREFETCH(kt+2, st2); commitg(); }
        const uint32_t stb = sb + A_ST(st);
        st2 = st;
        st = (st + 1 == 3) ? 0 : st + 1;

        if (kt == 0) {
            #pragma unroll
            for (int s = 0; s < 4; s++) {
                const int row = warp*16 + (grp & 1)*8 + wi;
                const int cb  = s*32 + (grp >> 1)*16;
                const uint32_t off = row*128 + ((uint32_t)cb ^ (uint32_t)((row & 7) << 4));
                ldsm4(sb + A_QH + off, qfh[s]);
            }
        }

        // ---- S = Q K^T ----
        float cS[8][4];
        #pragma unroll
        for (int nb = 0; nb < 8; nb++)
            #pragma unroll
            for (int j = 0; j < 4; j++) cS[nb][j] = 0.f;

        #pragma unroll
        for (int s = 0; s < 4; s++) {
            #pragma unroll
            for (int nbp = 0; nbp < 4; nbp++) {
                const int row = nbp*16 + (grp >> 1)*8 + wi;
                const int cb  = s*32 + (grp & 1)*16;
                const uint32_t off = row*128 + ((uint32_t)cb ^ (uint32_t)((row & 7) << 4));
                uint32_t kh4[4];
                ldsm4(stb + off, kh4);
                mma_f16(cS[2*nbp],   qfh[s], kh4[0], kh4[1]);
                mma_f16(cS[2*nbp+1], qfh[s], kh4[2], kh4[3]);
            }
        }

        // ---- scale + ALiBi + causal + online softmax ----
        const int r0 = qt*64 + warp*16 + g, r1 = r0 + 8;
        const bool diag = (kt == qt);
        float mx0 = -1e30f, mx1 = -1e30f;
        #pragma unroll
        for (int nb = 0; nb < 8; nb++) {
            const int k0i = kt*64 + nb*8 + t4*2;
            const float b0f = -slope2 * (float)(TT - 1 - k0i);
            const float b1f = -slope2 * (float)(TT - 2 - k0i);
            float v0 = fmaf(cS[nb][0], scale2, b0f);
            float v1 = fmaf(cS[nb][1], scale2, b1f);
            float v2 = fmaf(cS[nb][2], scale2, b0f);
            float v3 = fmaf(cS[nb][3], scale2, b1f);
            if (diag) {
                if (k0i     > r0) v0 = -1e30f;
                if (k0i + 1 > r0) v1 = -1e30f;
                if (k0i     > r1) v2 = -1e30f;
                if (k0i + 1 > r1) v3 = -1e30f;
            }
            cS[nb][0] = v0; cS[nb][1] = v1; cS[nb][2] = v2; cS[nb][3] = v3;
            mx0 = fmaxf(mx0, fmaxf(v0, v1));
            mx1 = fmaxf(mx1, fmaxf(v2, v3));
        }
        mx0 = fmaxf(mx0, __shfl_xor_sync(0xffffffffu, mx0, 1));
        mx0 = fmaxf(mx0, __shfl_xor_sync(0xffffffffu, mx0, 2));
        mx1 = fmaxf(mx1, __shfl_xor_sync(0xffffffffu, mx1, 1));
        mx1 = fmaxf(mx1, __shfl_xor_sync(0xffffffffu, mx1, 2));
        const float mn0 = fmaxf(mr0, mx0), mn1 = fmaxf(mr1, mx1);
        const float co0 = fast_exp2(mr0 - mn0), co1 = fast_exp2(mr1 - mn1);
        mr0 = mn0; mr1 = mn1;
        float s0 = 0.f, s1 = 0.f;
        #pragma unroll
        for (int nb = 0; nb < 8; nb++) {
            cS[nb][0] = fast_exp2(cS[nb][0] - mn0);
            cS[nb][1] = fast_exp2(cS[nb][1] - mn0);
            cS[nb][2] = fast_exp2(cS[nb][2] - mn1);
            cS[nb][3] = fast_exp2(cS[nb][3] - mn1);
            s0 += cS[nb][0] + cS[nb][1];
            s1 += cS[nb][2] + cS[nb][3];
        }
        s0 += __shfl_xor_sync(0xffffffffu, s0, 1);
        s0 += __shfl_xor_sync(0xffffffffu, s0, 2);
        s1 += __shfl_xor_sync(0xffffffffu, s1, 1);
        s1 += __shfl_xor_sync(0xffffffffu, s1, 2);
        lr0 = lr0 * co0 + s0;
        lr1 = lr1 * co1 + s1;
        #pragma unroll
        for (int nb = 0; nb < 8; nb++) {
            cO[nb][0] *= co0; cO[nb][1] *= co0;
            cO[nb][2] *= co1; cO[nb][3] *= co1;
        }

        // ---- O += P V ----
        #pragma unroll
        for (int s = 0; s < 4; s++) {
            uint32_t aP[4];
            aP[0] = pack2h(cS[2*s][0],   cS[2*s][1]);
            aP[1] = pack2h(cS[2*s][2],   cS[2*s][3]);
            aP[2] = pack2h(cS[2*s+1][0], cS[2*s+1][1]);
            aP[3] = pack2h(cS[2*s+1][2], cS[2*s+1][3]);
            #pragma unroll
            for (int nbp = 0; nbp < 4; nbp++) {
                const int row = s*16 + (grp & 1)*8 + wi;
                const int cb  = nbp*32 + (grp >> 1)*16;
                const uint32_t off = row*128 + ((uint32_t)cb ^ (uint32_t)((row & 7) << 4));
                uint32_t vh4[4];
                ldsm4t(stb + 8192 + off, vh4);
                mma_f16(cO[2*nbp],   aP, vh4[0], vh4[1]);
                mma_f16(cO[2*nbp+1], aP, vh4[2], vh4[3]);
            }
        }
    }

    // ---- normalize + write fp16 ----
    const float i0 = 1.f / lr0, i1 = 1.f / lr1;
    const int t0 = qt*64 + warp*16 + g;
    #pragma unroll
    for (int nb = 0; nb < 8; nb++) {
        const int d = h*HD + nb*8 + t4*2;
        const size_t o0 = (size_t)(b*TT + t0) * DD + d;
        const size_t o1 = o0 + (size_t)8 * DD;
        *(__half2*)(Oh + o0) = __floats2half2_rn(cO[nb][0]*i0, cO[nb][1]*i0);
        *(__half2*)(Oh + o1) = __floats2half2_rn(cO[nb][2]*i1, cO[nb][3]*i1);
    }
}

// ---------------------------------------------------------------------------
extern "C" void kernel_launch(void* const* d_in, const int* in_sizes, int n_in,
                              void* d_out, int out_size)
{
    const float* x  = (const float*)d_in[0];
    const float* Wq = (const float*)d_in[1];
    const float* bq = (const float*)d_in[2];
    const float* Wk = (const float*)d_in[3];
    const float* bk = (const float*)d_in[4];
    const float* Wv = (const float*)d_in[5];
    const float* bv = (const float*)d_in[6];
    const float* Wo = (const float*)d_in[7];
    const float* bo = (const float*)d_in[8];
    float* out = (float*)d_out;

    __half *xh,*qh,*kh,*vh,*ah,*wh;
    cudaGetSymbolAddress((void**)&xh, g_xh);
    cudaGetSymbolAddress((void**)&qh, g_qh);
    cudaGetSymbolAddress((void**)&kh, g_kh);
    cudaGetSymbolAddress((void**)&vh, g_vh);
    cudaGetSymbolAddress((void**)&ah, g_ah);
    cudaGetSymbolAddress((void**)&wh, g_wh);

    cudaFuncSetAttribute(mma_gemm<0>, cudaFuncAttributeMaxDynamicSharedMemorySize, GEMM_SMEM);
    cudaFuncSetAttribute(mma_gemm<1>, cudaFuncAttributeMaxDynamicSharedMemorySize, GEMM_SMEM);
    cudaFuncSetAttribute(attn_mma,   cudaFuncAttributeMaxDynamicSharedMemorySize, ATT_SMEM);

    const size_t WSZ = (size_t)DD * DD;

    tohalf<<<(MM*DD/4)/256, 256>>>(x, xh);
    transp4<<<dim3(32, 32, 4), dim3(32, 8)>>>(Wq, Wk, Wv, Wo, wh);

    mma_gemm<1><<<dim3(DD/128, MM/128, 3), 256, GEMM_SMEM>>>(
        xh, wh, bq, bk, bv, nullptr, qh, kh, vh);

    attn_mma<<<dim3(TT/64, BB*HH), 128, ATT_SMEM>>>(qh, kh, vh, ah);

    mma_gemm<0><<<dim3(DD/128, MM/128, 1), 256, GEMM_SMEM>>>(
        ah, wh + 3*WSZ, bo, bo, bo, out, nullptr, nullptr, nullptr);
}

// round 14
// speedup vs baseline: 1.8647x; 1.8647x over previous
#include <cuda_runtime.h>
#include <cuda_fp16.h>
#include <math.h>
#include <stdint.h>

#define BB 2
#define TT 2048
#define DD 1024
#define HH 16
#define HD 64
#define MM (BB*TT)

// ---------------- scratch ----------------
__device__ __half g_xh[(size_t)MM*DD];
__device__ __half g_qh[(size_t)MM*DD];
__device__ __half g_kh[(size_t)MM*DD];
__device__ __half g_vh[(size_t)MM*DD];
__device__ __half g_ah[(size_t)MM*DD];
__device__ __half g_wh[4*(size_t)DD*DD];

// ---------------- helpers ----------------
__device__ __forceinline__ uint32_t smem_u32(const void* p) {
    uint32_t a;
    asm("{ .reg .u64 t; cvta.to.shared.u64 t, %1; cvt.u32.u64 %0, t; }" : "=r"(a) : "l"(p));
    return a;
}
__device__ __forceinline__ float fast_exp2(float x) {
    float y; asm("ex2.approx.ftz.f32 %0, %1;" : "=f"(y) : "f"(x)); return y;
}
__device__ __forceinline__ void mma_f16(float* c, const uint32_t* a, uint32_t b0, uint32_t b1) {
    asm("mma.sync.aligned.m16n8k16.row.col.f32.f16.f16.f32 "
        "{%0,%1,%2,%3}, {%4,%5,%6,%7}, {%8,%9}, {%0,%1,%2,%3};"
        : "+f"(c[0]), "+f"(c[1]), "+f"(c[2]), "+f"(c[3])
        : "r"(a[0]), "r"(a[1]), "r"(a[2]), "r"(a[3]), "r"(b0), "r"(b1));
}
__device__ __forceinline__ void ldsm4(uint32_t addr, uint32_t* r) {
    asm volatile("ldmatrix.sync.aligned.m8n8.x4.shared.b16 {%0,%1,%2,%3}, [%4];"
        : "=r"(r[0]), "=r"(r[1]), "=r"(r[2]), "=r"(r[3]) : "r"(addr));
}
__device__ __forceinline__ void ldsm4t(uint32_t addr, uint32_t* r) {
    asm volatile("ldmatrix.sync.aligned.m8n8.x4.trans.shared.b16 {%0,%1,%2,%3}, [%4];"
        : "=r"(r[0]), "=r"(r[1]), "=r"(r[2]), "=r"(r[3]) : "r"(addr));
}
__device__ __forceinline__ void cpa(uint32_t dst, const void* src) {
    asm volatile("cp.async.ca.shared.global [%0], [%1], 16;" :: "r"(dst), "l"(src));
}
__device__ __forceinline__ void cpag(uint32_t dst, const void* src) {
    asm volatile("cp.async.cg.shared.global [%0], [%1], 16;" :: "r"(dst), "l"(src));
}
__device__ __forceinline__ void commitg() {
    asm volatile("cp.async.commit_group;" ::: "memory");
}
template<int N> __device__ __forceinline__ void waitg() {
    asm volatile("cp.async.wait_group %0;" :: "n"(N) : "memory");
}
__device__ __forceinline__ uint32_t pack2h(float x, float y) {
    uint32_t r; asm("cvt.rn.f16x2.f32 %0, %1, %2;" : "=r"(r) : "f"(y), "f"(x)); return r;
}

// ---------------------------------------------------------------------------
__global__ void tohalf(const float* __restrict__ in, __half* __restrict__ out)
{
    const int i = blockIdx.x * blockDim.x + threadIdx.x;
    float4 v = ((const float4*)in)[i];
    __half2* p = (__half2*)out;
    p[2*i]   = __floats2half2_rn(v.x, v.y);
    p[2*i+1] = __floats2half2_rn(v.z, v.w);
}

__global__ void transp4(const float* __restrict__ W0, const float* __restrict__ W1,
                        const float* __restrict__ W2, const float* __restrict__ W3,
                        __half* __restrict__ Bh)
{
    __shared__ float t[32][33];
    const int z = blockIdx.z;
    const float* A = (z == 0) ? W0 : (z == 1) ? W1 : (z == 2) ? W2 : W3;
    const size_t zo = (size_t)z * DD * DD;
    const int bx = blockIdx.x * 32, by = blockIdx.y * 32;
    const int x = threadIdx.x, y = threadIdx.y;
    #pragma unroll
    for (int i = 0; i < 32; i += 8)
        t[y + i][x] = A[(size_t)(by + y + i) * DD + bx + x];
    __syncthreads();
    #pragma unroll
    for (int i = 0; i < 32; i += 8)
        Bh[zo + (size_t)(bx + y + i) * DD + by + x] = __float2half_rn(t[x][y + i]);
}

// ---------------------------------------------------------------------------
// GEMM v3: plain fp16 mma.sync, BK=64 (16 iters), 2-stage cp.async (cg).
// Tiles 128 rows x 128B (SW128 swizzle). 1 sync/iter, compile-time stages.
// MODE 0: fp32 out. MODE 1: merged QKV, single-fp16 scatter to (B,H,T,hd).
// ---------------------------------------------------------------------------
#define G_A  0
#define G_B  16384
#define G_STG 32768
#define GEMM_SMEM 65536
#define NIT 16

#define GEMM_LOAD(IT, STG) { \
    const int k0_ = (IT) * 64; \
    _Pragma("unroll") \
    for (int q_ = 0; q_ < 8; q_++) { \
        int idx_ = q_ * 256 + tid; \
        int buf_ = idx_ >> 10, wi_ = idx_ & 1023; \
        int row_ = wi_ >> 3, ch_ = wi_ & 7; \
        uint32_t dst_ = sb + (STG)*G_STG + buf_*16384 + row_*128 + ((ch_ ^ (row_ & 7)) << 4); \
        const __half* src_ = buf_ ? (Bh + (size_t)(n0 + row_)*DD + k0_ + ch_*8) \
                                  : (Ah + (size_t)(m0 + row_)*DD + k0_ + ch_*8); \
        cpag(dst_, src_); \
    } }

template<int MODE>
__global__ __launch_bounds__(256, 2)
void mma_gemm(const __half* __restrict__ Ah, const __half* __restrict__ Wh,
              const float* __restrict__ b0, const float* __restrict__ b1,
              const float* __restrict__ b2,
              float* __restrict__ outf,
              __half* __restrict__ oh0, __half* __restrict__ oh1, __half* __restrict__ oh2)
{
    extern __shared__ __align__(1024) char smem[];
    const uint32_t sb = smem_u32(smem);
    const int tid  = threadIdx.x;
    const int wid  = tid >> 5, lane = tid & 31;
    const int g    = lane >> 2, t4 = lane & 3;
    const int grp  = lane >> 3, wi = lane & 7;
    const int wm   = wid & 3,  wn = wid >> 2;
    const int m0   = blockIdx.y * 128, n0 = blockIdx.x * 128;
    const int z    = blockIdx.z;

    const size_t WSZ = (size_t)DD * DD;
    const __half* Bh = Wh + (size_t)z * WSZ;
    const float* bias = (z == 0) ? b0 : (z == 1) ? b1 : b2;
    __half* outh = (z == 0) ? oh0 : (z == 1) ? oh1 : oh2;

    float c[2][8][4];
    #pragma unroll
    for (int mb = 0; mb < 2; mb++)
        #pragma unroll
        for (int nb = 0; nb < 8; nb++)
            #pragma unroll
            for (int j = 0; j < 4; j++) c[mb][nb][j] = 0.f;

    GEMM_LOAD(0, 0); commitg();

    for (int it = 0; it < NIT; it++) {
        waitg<0>();
        __syncthreads();
        if (it + 1 < NIT) { GEMM_LOAD(it+1, (it+1)&1); commitg(); }
        const uint32_t base = sb + (it & 1) * G_STG;

        #pragma unroll
        for (int ks = 0; ks < 4; ks++) {
            uint32_t ah[2][4];
            #pragma unroll
            for (int mb = 0; mb < 2; mb++) {
                const int row = wm*32 + mb*16 + (grp & 1)*8 + wi;
                const int cb  = ks*32 + (grp >> 1)*16;
                const uint32_t off = row*128 + ((uint32_t)cb ^ (uint32_t)((row & 7) << 4));
                ldsm4(base + G_A + off, ah[mb]);
            }
            #pragma unroll
            for (int nbp = 0; nbp < 4; nbp++) {
                const int rowb = wn*64 + nbp*16 + (grp >> 1)*8 + wi;
                const int cbb  = ks*32 + (grp & 1)*16;
                const uint32_t offb = rowb*128 + ((uint32_t)cbb ^ (uint32_t)((rowb & 7) << 4));
                uint32_t bh[4];
                ldsm4(base + G_B + offb, bh);
                #pragma unroll
                for (int mb = 0; mb < 2; mb++) {
                    mma_f16(c[mb][2*nbp],   ah[mb], bh[0], bh[1]);
                    mma_f16(c[mb][2*nbp+1], ah[mb], bh[2], bh[3]);
                }
            }
        }
    }

    #pragma unroll
    for (int mb = 0; mb < 2; mb++) {
        const int row = m0 + wm*32 + mb*16 + g;
        #pragma unroll
        for (int nb = 0; nb < 8; nb++) {
            const int col = n0 + wn*64 + nb*8 + t4*2;
            const float bx = bias[col], by = bias[col+1];
            const float v0x = c[mb][nb][0] + bx, v0y = c[mb][nb][1] + by;
            const float v1x = c[mb][nb][2] + bx, v1y = c[mb][nb][3] + by;
            if (MODE == 0) {
                *(float2*)(outf + (size_t)row * DD + col)       = make_float2(v0x, v0y);
                *(float2*)(outf + (size_t)(row + 8) * DD + col) = make_float2(v1x, v1y);
            } else {
                const int h = col >> 6, d = col & 63;
                const int b0r = row >> 11, t0 = row & (TT-1);
                const int b1r = (row+8) >> 11, t1 = (row+8) & (TT-1);
                const size_t o0 = (((size_t)(b0r*HH + h) * TT + t0) * HD) + d;
                const size_t o1 = (((size_t)(b1r*HH + h) * TT + t1) * HD) + d;
                *(__half2*)(outh + o0) = __floats2half2_rn(v0x, v0y);
                *(__half2*)(outh + o1) = __floats2half2_rn(v1x, v1y);
            }
        }
    }
}

// ---------------------------------------------------------------------------
// Flash attention (exact R12 version): single fp16, 64-query tiles,
// 128 threads, 3 CTAs/SM, 2-stage KV cp.async.
// SMEM 40KB: Q 8K + 2 stages x (K 8K + V 8K).
// ---------------------------------------------------------------------------
#define A_QH 0
#define A_ST(s) (8192 + (s)*16384)
#define ATT_SMEM 40960

#define KV_PREFETCH(KT, STG) { \
    _Pragma("unroll") \
    for (int q_ = 0; q_ < 8; q_++) { \
        int idx_ = q_ * 128 + tid; \
        int arr_ = idx_ >> 9, wi2_ = idx_ & 511; \
        int row_ = wi2_ >> 3, ch_ = wi2_ & 7; \
        uint32_t dst_ = sb + A_ST(STG) + arr_*8192 + row_*128 + ((ch_ ^ (row_ & 7)) << 4); \
        const __half* p_ = arr_ ? Vh : Kh; \
        cpa(dst_, p_ + bo + (size_t)((KT)*64 + row_)*HD + ch_*8); \
    } }

__global__ __launch_bounds__(128, 3)
void attn_mma(const __half* __restrict__ Qh,
              const __half* __restrict__ Kh, const __half* __restrict__ Vh,
              __half* __restrict__ Oh)
{
    extern __shared__ __align__(1024) char smem[];
    const uint32_t sb = smem_u32(smem);
    const int tid  = threadIdx.x, lane = tid & 31, warp = tid >> 5;
    const int g    = lane >> 2, t4 = lane & 3;
    const int grp  = lane >> 3, wi = lane & 7;
    const int qt   = (int)gridDim.x - 1 - (int)blockIdx.x;
    const int bh   = blockIdx.y, b = bh >> 4, h = bh & 15;
    const size_t bo = (size_t)bh * TT * HD;

    #pragma unroll
    for (int q = 0; q < 4; q++) {
        int idx = q * 128 + tid;
        int row = idx >> 3, ch = idx & 7;
        uint32_t dst = sb + A_QH + row*128 + ((ch ^ (row & 7)) << 4);
        cpa(dst, Qh + bo + (size_t)(qt*64 + row)*HD + ch*8);
    }
    KV_PREFETCH(0, 0); commitg();

    const float LOG2E  = 1.4426950408889634f;
    const float scale2 = 0.125f * LOG2E;
    const float slope2 = exp2f(-0.5f * (float)(h + 1)) * LOG2E;

    float cO[8][4];
    #pragma unroll
    for (int nb = 0; nb < 8; nb++)
        #pragma unroll
        for (int j = 0; j < 4; j++) cO[nb][j] = 0.f;
    float mr0 = -1e30f, mr1 = -1e30f, lr0 = 0.f, lr1 = 0.f;
    uint32_t qfh[4][4];

    for (int kt = 0; kt <= qt; kt++) {
        waitg<0>();
        __syncthreads();
        if (kt < qt) { KV_PREFETCH(kt+1, (kt+1)&1); commitg(); }
        const uint32_t stb = sb + A_ST(kt & 1);

        if (kt == 0) {
            #pragma unroll
            for (int s = 0; s < 4; s++) {
                const int row = warp*16 + (grp & 1)*8 + wi;
                const int cb  = s*32 + (grp >> 1)*16;
                const uint32_t off = row*128 + ((uint32_t)cb ^ (uint32_t)((row & 7) << 4));
                ldsm4(sb + A_QH + off, qfh[s]);
            }
        }

        // ---- S = Q K^T ----
        float cS[8][4];
        #pragma unroll
        for (int nb = 0; nb < 8; nb++)
            #pragma unroll
            for (int j = 0; j < 4; j++) cS[nb][j] = 0.f;

        #pragma unroll
        for (int s = 0; s < 4; s++) {
            #pragma unroll
            for (int nbp = 0; nbp < 4; nbp++) {
                const int row = nbp*16 + (grp >> 1)*8 + wi;
                const int cb  = s*32 + (grp & 1)*16;
                const uint32_t off = row*128 + ((uint32_t)cb ^ (uint32_t)((row & 7) << 4));
                uint32_t kh4[4];
                ldsm4(stb + off, kh4);
                mma_f16(cS[2*nbp],   qfh[s], kh4[0], kh4[1]);
                mma_f16(cS[2*nbp+1], qfh[s], kh4[2], kh4[3]);
            }
        }

        // ---- scale + ALiBi + causal + online softmax ----
        const int r0 = qt*64 + warp*16 + g, r1 = r0 + 8;
        const bool diag = (kt == qt);
        float mx0 = -1e30f, mx1 = -1e30f;
        #pragma unroll
        for (int nb = 0; nb < 8; nb++) {
            const int k0i = kt*64 + nb*8 + t4*2;
            const float b0f = -slope2 * (float)(TT - 1 - k0i);
            const float b1f = -slope2 * (float)(TT - 2 - k0i);
            float v0 = fmaf(cS[nb][0], scale2, b0f);
            float v1 = fmaf(cS[nb][1], scale2, b1f);
            float v2 = fmaf(cS[nb][2], scale2, b0f);
            float v3 = fmaf(cS[nb][3], scale2, b1f);
            if (diag) {
                if (k0i     > r0) v0 = -1e30f;
                if (k0i + 1 > r0) v1 = -1e30f;
                if (k0i     > r1) v2 = -1e30f;
                if (k0i + 1 > r1) v3 = -1e30f;
            }
            cS[nb][0] = v0; cS[nb][1] = v1; cS[nb][2] = v2; cS[nb][3] = v3;
            mx0 = fmaxf(mx0, fmaxf(v0, v1));
            mx1 = fmaxf(mx1, fmaxf(v2, v3));
        }
        mx0 = fmaxf(mx0, __shfl_xor_sync(0xffffffffu, mx0, 1));
        mx0 = fmaxf(mx0, __shfl_xor_sync(0xffffffffu, mx0, 2));
        mx1 = fmaxf(mx1, __shfl_xor_sync(0xffffffffu, mx1, 1));
        mx1 = fmaxf(mx1, __shfl_xor_sync(0xffffffffu, mx1, 2));
        const float mn0 = fmaxf(mr0, mx0), mn1 = fmaxf(mr1, mx1);
        const float co0 = fast_exp2(mr0 - mn0), co1 = fast_exp2(mr1 - mn1);
        mr0 = mn0; mr1 = mn1;
        float s0 = 0.f, s1 = 0.f;
        #pragma unroll
        for (int nb = 0; nb < 8; nb++) {
            cS[nb][0] = fast_exp2(cS[nb][0] - mn0);
            cS[nb][1] = fast_exp2(cS[nb][1] - mn0);
            cS[nb][2] = fast_exp2(cS[nb][2] - mn1);
            cS[nb][3] = fast_exp2(cS[nb][3] - mn1);
            s0 += cS[nb][0] + cS[nb][1];
            s1 += cS[nb][2] + cS[nb][3];
        }
        s0 += __shfl_xor_sync(0xffffffffu, s0, 1);
        s0 += __shfl_xor_sync(0xffffffffu, s0, 2);
        s1 += __shfl_xor_sync(0xffffffffu, s1, 1);
        s1 += __shfl_xor_sync(0xffffffffu, s1, 2);
        lr0 = lr0 * co0 + s0;
        lr1 = lr1 * co1 + s1;
        #pragma unroll
        for (int nb = 0; nb < 8; nb++) {
            cO[nb][0] *= co0; cO[nb][1] *= co0;
            cO[nb][2] *= co1; cO[nb][3] *= co1;
        }

        // ---- O += P V ----
        #pragma unroll
        for (int s = 0; s < 4; s++) {
            uint32_t aP[4];
            aP[0] = pack2h(cS[2*s][0],   cS[2*s][1]);
            aP[1] = pack2h(cS[2*s][2],   cS[2*s][3]);
            aP[2] = pack2h(cS[2*s+1][0], cS[2*s+1][1]);
            aP[3] = pack2h(cS[2*s+1][2], cS[2*s+1][3]);
            #pragma unroll
            for (int nbp = 0; nbp < 4; nbp++) {
                const int row = s*16 + (grp & 1)*8 + wi;
                const int cb  = nbp*32 + (grp >> 1)*16;
                const uint32_t off = row*128 + ((uint32_t)cb ^ (uint32_t)((row & 7) << 4));
                uint32_t vh4[4];
                ldsm4t(stb + 8192 + off, vh4);
                mma_f16(cO[2*nbp],   aP, vh4[0], vh4[1]);
                mma_f16(cO[2*nbp+1], aP, vh4[2], vh4[3]);
            }
        }
    }

    // ---- normalize + write fp16 ----
    const float i0 = 1.f / lr0, i1 = 1.f / lr1;
    const int t0 = qt*64 + warp*16 + g;
    #pragma unroll
    for (int nb = 0; nb < 8; nb++) {
        const int d = h*HD + nb*8 + t4*2;
        const size_t o0 = (size_t)(b*TT + t0) * DD + d;
        const size_t o1 = o0 + (size_t)8 * DD;
        *(__half2*)(Oh + o0) = __floats2half2_rn(cO[nb][0]*i0, cO[nb][1]*i0);
        *(__half2*)(Oh + o1) = __floats2half2_rn(cO[nb][2]*i1, cO[nb][3]*i1);
    }
}

// ---------------------------------------------------------------------------
extern "C" void kernel_launch(void* const* d_in, const int* in_sizes, int n_in,
                              void* d_out, int out_size)
{
    const float* x  = (const float*)d_in[0];
    const float* Wq = (const float*)d_in[1];
    const float* bq = (const float*)d_in[2];
    const float* Wk = (const float*)d_in[3];
    const float* bk = (const float*)d_in[4];
    const float* Wv = (const float*)d_in[5];
    const float* bv = (const float*)d_in[6];
    const float* Wo = (const float*)d_in[7];
    const float* bo = (const float*)d_in[8];
    float* out = (float*)d_out;

    __half *xh,*qh,*kh,*vh,*ah,*wh;
    cudaGetSymbolAddress((void**)&xh, g_xh);
    cudaGetSymbolAddress((void**)&qh, g_qh);
    cudaGetSymbolAddress((void**)&kh, g_kh);
    cudaGetSymbolAddress((void**)&vh, g_vh);
    cudaGetSymbolAddress((void**)&ah, g_ah);
    cudaGetSymbolAddress((void**)&wh, g_wh);

    cudaFuncSetAttribute(mma_gemm<0>, cudaFuncAttributeMaxDynamicSharedMemorySize, GEMM_SMEM);
    cudaFuncSetAttribute(mma_gemm<1>, cudaFuncAttributeMaxDynamicSharedMemorySize, GEMM_SMEM);
    cudaFuncSetAttribute(attn_mma,   cudaFuncAttributeMaxDynamicSharedMemorySize, ATT_SMEM);

    const size_t WSZ = (size_t)DD * DD;

    tohalf<<<(MM*DD/4)/256, 256>>>(x, xh);
    transp4<<<dim3(32, 32, 4), dim3(32, 8)>>>(Wq, Wk, Wv, Wo, wh);

    mma_gemm<1><<<dim3(DD/128, MM/128, 3), 256, GEMM_SMEM>>>(
        xh, wh, bq, bk, bv, nullptr, qh, kh, vh);

    attn_mma<<<dim3(TT/64, BB*HH), 128, ATT_SMEM>>>(qh, kh, vh, ah);

    mma_gemm<0><<<dim3(DD/128, MM/128, 1), 256, GEMM_SMEM>>>(
        ah, wh + 3*WSZ, bo, bo, bo, out, nullptr, nullptr, nullptr);
}

// round 15
// speedup vs baseline: 1.9350x; 1.0377x over previous
#include <cuda_runtime.h>
#include <cuda_fp16.h>
#include <math.h>
#include <stdint.h>

#define BB 2
#define TT 2048
#define DD 1024
#define HH 16
#define HD 64
#define MM (BB*TT)

// ---------------- scratch ----------------
__device__ __half g_xh[(size_t)MM*DD];
__device__ __half g_qh[(size_t)MM*DD];
__device__ __half g_kh[(size_t)MM*DD];
__device__ __half g_vh[(size_t)MM*DD];
__device__ __half g_ah[(size_t)MM*DD];
__device__ __half g_wh[4*(size_t)DD*DD];

// ---------------- helpers ----------------
__device__ __forceinline__ uint32_t smem_u32(const void* p) {
    uint32_t a;
    asm("{ .reg .u64 t; cvta.to.shared.u64 t, %1; cvt.u32.u64 %0, t; }" : "=r"(a) : "l"(p));
    return a;
}
__device__ __forceinline__ float fast_exp2(float x) {
    float y; asm("ex2.approx.ftz.f32 %0, %1;" : "=f"(y) : "f"(x)); return y;
}
__device__ __forceinline__ void mma_f16(float* c, const uint32_t* a, uint32_t b0, uint32_t b1) {
    asm("mma.sync.aligned.m16n8k16.row.col.f32.f16.f16.f32 "
        "{%0,%1,%2,%3}, {%4,%5,%6,%7}, {%8,%9}, {%0,%1,%2,%3};"
        : "+f"(c[0]), "+f"(c[1]), "+f"(c[2]), "+f"(c[3])
        : "r"(a[0]), "r"(a[1]), "r"(a[2]), "r"(a[3]), "r"(b0), "r"(b1));
}
__device__ __forceinline__ void ldsm4(uint32_t addr, uint32_t* r) {
    asm volatile("ldmatrix.sync.aligned.m8n8.x4.shared.b16 {%0,%1,%2,%3}, [%4];"
        : "=r"(r[0]), "=r"(r[1]), "=r"(r[2]), "=r"(r[3]) : "r"(addr));
}
__device__ __forceinline__ void ldsm4t(uint32_t addr, uint32_t* r) {
    asm volatile("ldmatrix.sync.aligned.m8n8.x4.trans.shared.b16 {%0,%1,%2,%3}, [%4];"
        : "=r"(r[0]), "=r"(r[1]), "=r"(r[2]), "=r"(r[3]) : "r"(addr));
}
__device__ __forceinline__ void cpa(uint32_t dst, const void* src) {
    asm volatile("cp.async.ca.shared.global [%0], [%1], 16;" :: "r"(dst), "l"(src));
}
__device__ __forceinline__ void cpag(uint32_t dst, const void* src) {
    asm volatile("cp.async.cg.shared.global [%0], [%1], 16;" :: "r"(dst), "l"(src));
}
__device__ __forceinline__ void commitg() {
    asm volatile("cp.async.commit_group;" ::: "memory");
}
template<int N> __device__ __forceinline__ void waitg() {
    asm volatile("cp.async.wait_group %0;" :: "n"(N) : "memory");
}
__device__ __forceinline__ uint32_t pack2h(float x, float y) {
    uint32_t r; asm("cvt.rn.f16x2.f32 %0, %1, %2;" : "=r"(r) : "f"(y), "f"(x)); return r;
}

// ---------------------------------------------------------------------------
__global__ void tohalf(const float* __restrict__ in, __half* __restrict__ out)
{
    const int i = blockIdx.x * blockDim.x + threadIdx.x;
    float4 v = ((const float4*)in)[i];
    __half2* p = (__half2*)out;
    p[2*i]   = __floats2half2_rn(v.x, v.y);
    p[2*i+1] = __floats2half2_rn(v.z, v.w);
}

__global__ void transp4(const float* __restrict__ W0, const float* __restrict__ W1,
                        const float* __restrict__ W2, const float* __restrict__ W3,
                        __half* __restrict__ Bh)
{
    __shared__ float t[32][33];
    const int z = blockIdx.z;
    const float* A = (z == 0) ? W0 : (z == 1) ? W1 : (z == 2) ? W2 : W3;
    const size_t zo = (size_t)z * DD * DD;
    const int bx = blockIdx.x * 32, by = blockIdx.y * 32;
    const int x = threadIdx.x, y = threadIdx.y;
    #pragma unroll
    for (int i = 0; i < 32; i += 8)
        t[y + i][x] = A[(size_t)(by + y + i) * DD + bx + x];
    __syncthreads();
    #pragma unroll
    for (int i = 0; i < 32; i += 8)
        Bh[zo + (size_t)(bx + y + i) * DD + by + x] = __float2half_rn(t[x][y + i]);
}

// ---------------------------------------------------------------------------
// GEMM (exact R14): plain fp16 mma.sync, BK=64 (16 iters), 2-stage cp.async.cg.
// ---------------------------------------------------------------------------
#define G_A  0
#define G_B  16384
#define G_STG 32768
#define GEMM_SMEM 65536
#define NIT 16

#define GEMM_LOAD(IT, STG) { \
    const int k0_ = (IT) * 64; \
    _Pragma("unroll") \
    for (int q_ = 0; q_ < 8; q_++) { \
        int idx_ = q_ * 256 + tid; \
        int buf_ = idx_ >> 10, wi_ = idx_ & 1023; \
        int row_ = wi_ >> 3, ch_ = wi_ & 7; \
        uint32_t dst_ = sb + (STG)*G_STG + buf_*16384 + row_*128 + ((ch_ ^ (row_ & 7)) << 4); \
        const __half* src_ = buf_ ? (Bh + (size_t)(n0 + row_)*DD + k0_ + ch_*8) \
                                  : (Ah + (size_t)(m0 + row_)*DD + k0_ + ch_*8); \
        cpag(dst_, src_); \
    } }

template<int MODE>
__global__ __launch_bounds__(256, 2)
void mma_gemm(const __half* __restrict__ Ah, const __half* __restrict__ Wh,
              const float* __restrict__ b0, const float* __restrict__ b1,
              const float* __restrict__ b2,
              float* __restrict__ outf,
              __half* __restrict__ oh0, __half* __restrict__ oh1, __half* __restrict__ oh2)
{
    extern __shared__ __align__(1024) char smem[];
    const uint32_t sb = smem_u32(smem);
    const int tid  = threadIdx.x;
    const int wid  = tid >> 5, lane = tid & 31;
    const int g    = lane >> 2, t4 = lane & 3;
    const int grp  = lane >> 3, wi = lane & 7;
    const int wm   = wid & 3,  wn = wid >> 2;
    const int m0   = blockIdx.y * 128, n0 = blockIdx.x * 128;
    const int z    = blockIdx.z;

    const size_t WSZ = (size_t)DD * DD;
    const __half* Bh = Wh + (size_t)z * WSZ;
    const float* bias = (z == 0) ? b0 : (z == 1) ? b1 : b2;
    __half* outh = (z == 0) ? oh0 : (z == 1) ? oh1 : oh2;

    float c[2][8][4];
    #pragma unroll
    for (int mb = 0; mb < 2; mb++)
        #pragma unroll
        for (int nb = 0; nb < 8; nb++)
            #pragma unroll
            for (int j = 0; j < 4; j++) c[mb][nb][j] = 0.f;

    GEMM_LOAD(0, 0); commitg();

    for (int it = 0; it < NIT; it++) {
        waitg<0>();
        __syncthreads();
        if (it + 1 < NIT) { GEMM_LOAD(it+1, (it+1)&1); commitg(); }
        const uint32_t base = sb + (it & 1) * G_STG;

        #pragma unroll
        for (int ks = 0; ks < 4; ks++) {
            uint32_t ah[2][4];
            #pragma unroll
            for (int mb = 0; mb < 2; mb++) {
                const int row = wm*32 + mb*16 + (grp & 1)*8 + wi;
                const int cb  = ks*32 + (grp >> 1)*16;
                const uint32_t off = row*128 + ((uint32_t)cb ^ (uint32_t)((row & 7) << 4));
                ldsm4(base + G_A + off, ah[mb]);
            }
            #pragma unroll
            for (int nbp = 0; nbp < 4; nbp++) {
                const int rowb = wn*64 + nbp*16 + (grp >> 1)*8 + wi;
                const int cbb  = ks*32 + (grp & 1)*16;
                const uint32_t offb = rowb*128 + ((uint32_t)cbb ^ (uint32_t)((rowb & 7) << 4));
                uint32_t bh[4];
                ldsm4(base + G_B + offb, bh);
                #pragma unroll
                for (int mb = 0; mb < 2; mb++) {
                    mma_f16(c[mb][2*nbp],   ah[mb], bh[0], bh[1]);
                    mma_f16(c[mb][2*nbp+1], ah[mb], bh[2], bh[3]);
                }
            }
        }
    }

    #pragma unroll
    for (int mb = 0; mb < 2; mb++) {
        const int row = m0 + wm*32 + mb*16 + g;
        #pragma unroll
        for (int nb = 0; nb < 8; nb++) {
            const int col = n0 + wn*64 + nb*8 + t4*2;
            const float bx = bias[col], by = bias[col+1];
            const float v0x = c[mb][nb][0] + bx, v0y = c[mb][nb][1] + by;
            const float v1x = c[mb][nb][2] + bx, v1y = c[mb][nb][3] + by;
            if (MODE == 0) {
                *(float2*)(outf + (size_t)row * DD + col)       = make_float2(v0x, v0y);
                *(float2*)(outf + (size_t)(row + 8) * DD + col) = make_float2(v1x, v1y);
            } else {
                const int h = col >> 6, d = col & 63;
                const int b0r = row >> 11, t0 = row & (TT-1);
                const int b1r = (row+8) >> 11, t1 = (row+8) & (TT-1);
                const size_t o0 = (((size_t)(b0r*HH + h) * TT + t0) * HD) + d;
                const size_t o1 = (((size_t)(b1r*HH + h) * TT + t1) * HD) + d;
                *(__half2*)(outh + o0) = __floats2half2_rn(v0x, v0y);
                *(__half2*)(outh + o1) = __floats2half2_rn(v1x, v1y);
            }
        }
    }
}

// ---------------------------------------------------------------------------
// Flash attention v5: single fp16, 64-query tiles, 128 threads, 3 CTAs/SM.
// NO online max: per-row fixed shift = ALiBi bias at the causal frontier
// (bias is monotone in key pos, so frontier bias is its max over allowed keys;
// scale2*S is statistically bounded, so exp2 in f32 cannot overflow, and
// far-key underflow to 0 matches the reference's ~0 weights).
// logit' = scale2*S + slope2*(j - r). No corr, no cO rescale, plain l sum.
// ---------------------------------------------------------------------------
#define A_QH 0
#define A_ST(s) (8192 + (s)*16384)
#define ATT_SMEM 40960

#define KV_PREFETCH(KT, STG) { \
    _Pragma("unroll") \
    for (int q_ = 0; q_ < 8; q_++) { \
        int idx_ = q_ * 128 + tid; \
        int arr_ = idx_ >> 9, wi2_ = idx_ & 511; \
        int row_ = wi2_ >> 3, ch_ = wi2_ & 7; \
        uint32_t dst_ = sb + A_ST(STG) + arr_*8192 + row_*128 + ((ch_ ^ (row_ & 7)) << 4); \
        const __half* p_ = arr_ ? Vh : Kh; \
        cpa(dst_, p_ + bo + (size_t)((KT)*64 + row_)*HD + ch_*8); \
    } }

__global__ __launch_bounds__(128, 3)
void attn_mma(const __half* __restrict__ Qh,
              const __half* __restrict__ Kh, const __half* __restrict__ Vh,
              __half* __restrict__ Oh)
{
    extern __shared__ __align__(1024) char smem[];
    const uint32_t sb = smem_u32(smem);
    const int tid  = threadIdx.x, lane = tid & 31, warp = tid >> 5;
    const int g    = lane >> 2, t4 = lane & 3;
    const int grp  = lane >> 3, wi = lane & 7;
    const int qt   = (int)gridDim.x - 1 - (int)blockIdx.x;
    const int bh   = blockIdx.y, b = bh >> 4, h = bh & 15;
    const size_t bo = (size_t)bh * TT * HD;

    #pragma unroll
    for (int q = 0; q < 4; q++) {
        int idx = q * 128 + tid;
        int row = idx >> 3, ch = idx & 7;
        uint32_t dst = sb + A_QH + row*128 + ((ch ^ (row & 7)) << 4);
        cpa(dst, Qh + bo + (size_t)(qt*64 + row)*HD + ch*8);
    }
    KV_PREFETCH(0, 0); commitg();

    const float LOG2E  = 1.4426950408889634f;
    const float scale2 = 0.125f * LOG2E;
    const float slope2 = exp2f(-0.5f * (float)(h + 1)) * LOG2E;

    float cO[8][4];
    #pragma unroll
    for (int nb = 0; nb < 8; nb++)
        #pragma unroll
        for (int j = 0; j < 4; j++) cO[nb][j] = 0.f;
    float lr0 = 0.f, lr1 = 0.f;
    uint32_t qfh[4][4];

    const int r0 = qt*64 + warp*16 + g, r1 = r0 + 8;

    for (int kt = 0; kt <= qt; kt++) {
        waitg<0>();
        __syncthreads();
        if (kt < qt) { KV_PREFETCH(kt+1, (kt+1)&1); commitg(); }
        const uint32_t stb = sb + A_ST(kt & 1);

        if (kt == 0) {
            #pragma unroll
            for (int s = 0; s < 4; s++) {
                const int row = warp*16 + (grp & 1)*8 + wi;
                const int cb  = s*32 + (grp >> 1)*16;
                const uint32_t off = row*128 + ((uint32_t)cb ^ (uint32_t)((row & 7) << 4));
                ldsm4(sb + A_QH + off, qfh[s]);
            }
        }

        // ---- S = Q K^T ----
        float cS[8][4];
        #pragma unroll
        for (int nb = 0; nb < 8; nb++)
            #pragma unroll
            for (int j = 0; j < 4; j++) cS[nb][j] = 0.f;

        #pragma unroll
        for (int s = 0; s < 4; s++) {
            #pragma unroll
            for (int nbp = 0; nbp < 4; nbp++) {
                const int row = nbp*16 + (grp >> 1)*8 + wi;
                const int cb  = s*32 + (grp & 1)*16;
                const uint32_t off = row*128 + ((uint32_t)cb ^ (uint32_t)((row & 7) << 4));
                uint32_t kh4[4];
                ldsm4(stb + off, kh4);
                mma_f16(cS[2*nbp],   qfh[s], kh4[0], kh4[1]);
                mma_f16(cS[2*nbp+1], qfh[s], kh4[2], kh4[3]);
            }
        }

        // ---- fixed-shift softmax: p = exp2(scale2*S + slope2*(j - r)) ----
        const bool diag = (kt == qt);
        float s0 = 0.f, s1 = 0.f;
        #pragma unroll
        for (int nb = 0; nb < 8; nb++) {
            const int k0i = kt*64 + nb*8 + t4*2;
            const float d00 = slope2 * (float)(k0i     - r0);
            const float d01 = slope2 * (float)(k0i + 1 - r0);
            const float d10 = slope2 * (float)(k0i     - r1);
            const float d11 = slope2 * (float)(k0i + 1 - r1);
            float v0 = fmaf(cS[nb][0], scale2, d00);
            float v1 = fmaf(cS[nb][1], scale2, d01);
            float v2 = fmaf(cS[nb][2], scale2, d10);
            float v3 = fmaf(cS[nb][3], scale2, d11);
            if (diag) {
                if (k0i     > r0) v0 = -1e30f;
                if (k0i + 1 > r0) v1 = -1e30f;
                if (k0i     > r1) v2 = -1e30f;
                if (k0i + 1 > r1) v3 = -1e30f;
            }
            const float p0 = fast_exp2(v0);
            const float p1 = fast_exp2(v1);
            const float p2 = fast_exp2(v2);
            const float p3 = fast_exp2(v3);
            cS[nb][0] = p0; cS[nb][1] = p1; cS[nb][2] = p2; cS[nb][3] = p3;
            s0 += p0 + p1;
            s1 += p2 + p3;
        }
        lr0 += s0;
        lr1 += s1;

        // ---- O += P V ----
        #pragma unroll
        for (int s = 0; s < 4; s++) {
            uint32_t aP[4];
            aP[0] = pack2h(cS[2*s][0],   cS[2*s][1]);
            aP[1] = pack2h(cS[2*s][2],   cS[2*s][3]);
            aP[2] = pack2h(cS[2*s+1][0], cS[2*s+1][1]);
            aP[3] = pack2h(cS[2*s+1][2], cS[2*s+1][3]);
            #pragma unroll
            for (int nbp = 0; nbp < 4; nbp++) {
                const int row = s*16 + (grp & 1)*8 + wi;
                const int cb  = nbp*32 + (grp >> 1)*16;
                const uint32_t off = row*128 + ((uint32_t)cb ^ (uint32_t)((row & 7) << 4));
                uint32_t vh4[4];
                ldsm4t(stb + 8192 + off, vh4);
                mma_f16(cO[2*nbp],   aP, vh4[0], vh4[1]);
                mma_f16(cO[2*nbp+1], aP, vh4[2], vh4[3]);
            }
        }
    }

    // ---- cross-lane l reduction + normalize + write fp16 ----
    lr0 += __shfl_xor_sync(0xffffffffu, lr0, 1);
    lr0 += __shfl_xor_sync(0xffffffffu, lr0, 2);
    lr1 += __shfl_xor_sync(0xffffffffu, lr1, 1);
    lr1 += __shfl_xor_sync(0xffffffffu, lr1, 2);
    const float i0 = 1.f / lr0, i1 = 1.f / lr1;
    const int t0 = qt*64 + warp*16 + g;
    #pragma unroll
    for (int nb = 0; nb < 8; nb++) {
        const int d = h*HD + nb*8 + t4*2;
        const size_t o0 = (size_t)(b*TT + t0) * DD + d;
        const size_t o1 = o0 + (size_t)8 * DD;
        *(__half2*)(Oh + o0) = __floats2half2_rn(cO[nb][0]*i0, cO[nb][1]*i0);
        *(__half2*)(Oh + o1) = __floats2half2_rn(cO[nb][2]*i1, cO[nb][3]*i1);
    }
}

// ---------------------------------------------------------------------------
extern "C" void kernel_launch(void* const* d_in, const int* in_sizes, int n_in,
                              void* d_out, int out_size)
{
    const float* x  = (const float*)d_in[0];
    const float* Wq = (const float*)d_in[1];
    const float* bq = (const float*)d_in[2];
    const float* Wk = (const float*)d_in[3];
    const float* bk = (const float*)d_in[4];
    const float* Wv = (const float*)d_in[5];
    const float* bv = (const float*)d_in[6];
    const float* Wo = (const float*)d_in[7];
    const float* bo = (const float*)d_in[8];
    float* out = (float*)d_out;

    __half *xh,*qh,*kh,*vh,*ah,*wh;
    cudaGetSymbolAddress((void**)&xh, g_xh);
    cudaGetSymbolAddress((void**)&qh, g_qh);
    cudaGetSymbolAddress((void**)&kh, g_kh);
    cudaGetSymbolAddress((void**)&vh, g_vh);
    cudaGetSymbolAddress((void**)&ah, g_ah);
    cudaGetSymbolAddress((void**)&wh, g_wh);

    cudaFuncSetAttribute(mma_gemm<0>, cudaFuncAttributeMaxDynamicSharedMemorySize, GEMM_SMEM);
    cudaFuncSetAttribute(mma_gemm<1>, cudaFuncAttributeMaxDynamicSharedMemorySize, GEMM_SMEM);
    cudaFuncSetAttribute(attn_mma,   cudaFuncAttributeMaxDynamicSharedMemorySize, ATT_SMEM);

    const size_t WSZ = (size_t)DD * DD;

    tohalf<<<(MM*DD/4)/256, 256>>>(x, xh);
    transp4<<<dim3(32, 32, 4), dim3(32, 8)>>>(Wq, Wk, Wv, Wo, wh);

    mma_gemm<1><<<dim3(DD/128, MM/128, 3), 256, GEMM_SMEM>>>(
        xh, wh, bq, bk, bv, nullptr, qh, kh, vh);

    attn_mma<<<dim3(TT/64, BB*HH), 128, ATT_SMEM>>>(qh, kh, vh, ah);

    mma_gemm<0><<<dim3(DD/128, MM/128, 1), 256, GEMM_SMEM>>>(
        ah, wh + 3*WSZ, bo, bo, bo, out, nullptr, nullptr, nullptr);
}

// round 16
// speedup vs baseline: 1.9566x; 1.0112x over previous
#include <cuda_runtime.h>
#include <cuda_fp16.h>
#include <math.h>
#include <stdint.h>

#define BB 2
#define TT 2048
#define DD 1024
#define HH 16
#define HD 64
#define MM (BB*TT)

// ---------------- scratch ----------------
__device__ __half g_xh[(size_t)MM*DD];
__device__ __half g_qh[(size_t)MM*DD];
__device__ __half g_kh[(size_t)MM*DD];
__device__ __half g_vh[(size_t)MM*DD];
__device__ __half g_ah[(size_t)MM*DD];
__device__ __half g_wh[4*(size_t)DD*DD];

// ---------------- helpers ----------------
__device__ __forceinline__ uint32_t smem_u32(const void* p) {
    uint32_t a;
    asm("{ .reg .u64 t; cvta.to.shared.u64 t, %1; cvt.u32.u64 %0, t; }" : "=r"(a) : "l"(p));
    return a;
}
__device__ __forceinline__ void mma_f16(float* c, const uint32_t* a, uint32_t b0, uint32_t b1) {
    asm("mma.sync.aligned.m16n8k16.row.col.f32.f16.f16.f32 "
        "{%0,%1,%2,%3}, {%4,%5,%6,%7}, {%8,%9}, {%0,%1,%2,%3};"
        : "+f"(c[0]), "+f"(c[1]), "+f"(c[2]), "+f"(c[3])
        : "r"(a[0]), "r"(a[1]), "r"(a[2]), "r"(a[3]), "r"(b0), "r"(b1));
}
__device__ __forceinline__ void ldsm4(uint32_t addr, uint32_t* r) {
    asm volatile("ldmatrix.sync.aligned.m8n8.x4.shared.b16 {%0,%1,%2,%3}, [%4];"
        : "=r"(r[0]), "=r"(r[1]), "=r"(r[2]), "=r"(r[3]) : "r"(addr));
}
__device__ __forceinline__ void ldsm4t(uint32_t addr, uint32_t* r) {
    asm volatile("ldmatrix.sync.aligned.m8n8.x4.trans.shared.b16 {%0,%1,%2,%3}, [%4];"
        : "=r"(r[0]), "=r"(r[1]), "=r"(r[2]), "=r"(r[3]) : "r"(addr));
}
__device__ __forceinline__ void cpa(uint32_t dst, const void* src) {
    asm volatile("cp.async.ca.shared.global [%0], [%1], 16;" :: "r"(dst), "l"(src));
}
__device__ __forceinline__ void cpag(uint32_t dst, const void* src) {
    asm volatile("cp.async.cg.shared.global [%0], [%1], 16;" :: "r"(dst), "l"(src));
}
__device__ __forceinline__ void commitg() {
    asm volatile("cp.async.commit_group;" ::: "memory");
}
template<int N> __device__ __forceinline__ void waitg() {
    asm volatile("cp.async.wait_group %0;" :: "n"(N) : "memory");
}
__device__ __forceinline__ uint32_t pack2h(float x, float y) {
    uint32_t r; asm("cvt.rn.f16x2.f32 %0, %1, %2;" : "=r"(r) : "f"(y), "f"(x)); return r;
}
__device__ __forceinline__ uint32_t exp2_h2(uint32_t x) {
    uint32_t r; asm("ex2.approx.f16x2 %0, %1;" : "=r"(r) : "r"(x)); return r;
}

// ---------------------------------------------------------------------------
__global__ void tohalf(const float* __restrict__ in, __half* __restrict__ out)
{
    const int i = blockIdx.x * blockDim.x + threadIdx.x;
    float4 v = ((const float4*)in)[i];
    __half2* p = (__half2*)out;
    p[2*i]   = __floats2half2_rn(v.x, v.y);
    p[2*i+1] = __floats2half2_rn(v.z, v.w);
}

__global__ void transp4(const float* __restrict__ W0, const float* __restrict__ W1,
                        const float* __restrict__ W2, const float* __restrict__ W3,
                        __half* __restrict__ Bh)
{
    __shared__ float t[32][33];
    const int z = blockIdx.z;
    const float* A = (z == 0) ? W0 : (z == 1) ? W1 : (z == 2) ? W2 : W3;
    const size_t zo = (size_t)z * DD * DD;
    const int bx = blockIdx.x * 32, by = blockIdx.y * 32;
    const int x = threadIdx.x, y = threadIdx.y;
    #pragma unroll
    for (int i = 0; i < 32; i += 8)
        t[y + i][x] = A[(size_t)(by + y + i) * DD + bx + x];
    __syncthreads();
    #pragma unroll
    for (int i = 0; i < 32; i += 8)
        Bh[zo + (size_t)(bx + y + i) * DD + by + x] = __float2half_rn(t[x][y + i]);
}

// ---------------------------------------------------------------------------
// GEMM (exact R14): plain fp16 mma.sync, BK=64 (16 iters), 2-stage cp.async.cg.
// ---------------------------------------------------------------------------
#define G_A  0
#define G_B  16384
#define G_STG 32768
#define GEMM_SMEM 65536
#define NIT 16

#define GEMM_LOAD(IT, STG) { \
    const int k0_ = (IT) * 64; \
    _Pragma("unroll") \
    for (int q_ = 0; q_ < 8; q_++) { \
        int idx_ = q_ * 256 + tid; \
        int buf_ = idx_ >> 10, wi_ = idx_ & 1023; \
        int row_ = wi_ >> 3, ch_ = wi_ & 7; \
        uint32_t dst_ = sb + (STG)*G_STG + buf_*16384 + row_*128 + ((ch_ ^ (row_ & 7)) << 4); \
        const __half* src_ = buf_ ? (Bh + (size_t)(n0 + row_)*DD + k0_ + ch_*8) \
                                  : (Ah + (size_t)(m0 + row_)*DD + k0_ + ch_*8); \
        cpag(dst_, src_); \
    } }

template<int MODE>
__global__ __launch_bounds__(256, 2)
void mma_gemm(const __half* __restrict__ Ah, const __half* __restrict__ Wh,
              const float* __restrict__ b0, const float* __restrict__ b1,
              const float* __restrict__ b2,
              float* __restrict__ outf,
              __half* __restrict__ oh0, __half* __restrict__ oh1, __half* __restrict__ oh2)
{
    extern __shared__ __align__(1024) char smem[];
    const uint32_t sb = smem_u32(smem);
    const int tid  = threadIdx.x;
    const int wid  = tid >> 5, lane = tid & 31;
    const int g    = lane >> 2, t4 = lane & 3;
    const int grp  = lane >> 3, wi = lane & 7;
    const int wm   = wid & 3,  wn = wid >> 2;
    const int m0   = blockIdx.y * 128, n0 = blockIdx.x * 128;
    const int z    = blockIdx.z;

    const size_t WSZ = (size_t)DD * DD;
    const __half* Bh = Wh + (size_t)z * WSZ;
    const float* bias = (z == 0) ? b0 : (z == 1) ? b1 : b2;
    __half* outh = (z == 0) ? oh0 : (z == 1) ? oh1 : oh2;

    float c[2][8][4];
    #pragma unroll
    for (int mb = 0; mb < 2; mb++)
        #pragma unroll
        for (int nb = 0; nb < 8; nb++)
            #pragma unroll
            for (int j = 0; j < 4; j++) c[mb][nb][j] = 0.f;

    GEMM_LOAD(0, 0); commitg();

    for (int it = 0; it < NIT; it++) {
        waitg<0>();
        __syncthreads();
        if (it + 1 < NIT) { GEMM_LOAD(it+1, (it+1)&1); commitg(); }
        const uint32_t base = sb + (it & 1) * G_STG;

        #pragma unroll
        for (int ks = 0; ks < 4; ks++) {
            uint32_t ah[2][4];
            #pragma unroll
            for (int mb = 0; mb < 2; mb++) {
                const int row = wm*32 + mb*16 + (grp & 1)*8 + wi;
                const int cb  = ks*32 + (grp >> 1)*16;
                const uint32_t off = row*128 + ((uint32_t)cb ^ (uint32_t)((row & 7) << 4));
                ldsm4(base + G_A + off, ah[mb]);
            }
            #pragma unroll
            for (int nbp = 0; nbp < 4; nbp++) {
                const int rowb = wn*64 + nbp*16 + (grp >> 1)*8 + wi;
                const int cbb  = ks*32 + (grp & 1)*16;
                const uint32_t offb = rowb*128 + ((uint32_t)cbb ^ (uint32_t)((rowb & 7) << 4));
                uint32_t bh[4];
                ldsm4(base + G_B + offb, bh);
                #pragma unroll
                for (int mb = 0; mb < 2; mb++) {
                    mma_f16(c[mb][2*nbp],   ah[mb], bh[0], bh[1]);
                    mma_f16(c[mb][2*nbp+1], ah[mb], bh[2], bh[3]);
                }
            }
        }
    }

    #pragma unroll
    for (int mb = 0; mb < 2; mb++) {
        const int row = m0 + wm*32 + mb*16 + g;
        #pragma unroll
        for (int nb = 0; nb < 8; nb++) {
            const int col = n0 + wn*64 + nb*8 + t4*2;
            const float bx = bias[col], by = bias[col+1];
            const float v0x = c[mb][nb][0] + bx, v0y = c[mb][nb][1] + by;
            const float v1x = c[mb][nb][2] + bx, v1y = c[mb][nb][3] + by;
            if (MODE == 0) {
                *(float2*)(outf + (size_t)row * DD + col)       = make_float2(v0x, v0y);
                *(float2*)(outf + (size_t)(row + 8) * DD + col) = make_float2(v1x, v1y);
            } else {
                const int h = col >> 6, d = col & 63;
                const int b0r = row >> 11, t0 = row & (TT-1);
                const int b1r = (row+8) >> 11, t1 = (row+8) & (TT-1);
                const size_t o0 = (((size_t)(b0r*HH + h) * TT + t0) * HD) + d;
                const size_t o1 = (((size_t)(b1r*HH + h) * TT + t1) * HD) + d;
                *(__half2*)(outh + o0) = __floats2half2_rn(v0x, v0y);
                *(__half2*)(outh + o1) = __floats2half2_rn(v1x, v1y);
            }
        }
    }
}

// ---------------------------------------------------------------------------
// Flash attention v6: single fp16, 64-query tiles, 128 threads, 3 CTAs/SM.
// Fixed-shift softmax (frontier ALiBi shift), exp via ex2.approx.f16x2
// (output IS the P a-frag register), row-sum l via ones-vector MMA
// (accumulated in a c-frag; every lane holds its own row's full sum).
// ---------------------------------------------------------------------------
#define A_QH 0
#define A_ST(s) (8192 + (s)*16384)
#define ATT_SMEM 40960
#define ONES2 0x3C003C00u

#define KV_PREFETCH(KT, STG) { \
    _Pragma("unroll") \
    for (int q_ = 0; q_ < 8; q_++) { \
        int idx_ = q_ * 128 + tid; \
        int arr_ = idx_ >> 9, wi2_ = idx_ & 511; \
        int row_ = wi2_ >> 3, ch_ = wi2_ & 7; \
        uint32_t dst_ = sb + A_ST(STG) + arr_*8192 + row_*128 + ((ch_ ^ (row_ & 7)) << 4); \
        const __half* p_ = arr_ ? Vh : Kh; \
        cpa(dst_, p_ + bo + (size_t)((KT)*64 + row_)*HD + ch_*8); \
    } }

__global__ __launch_bounds__(128, 3)
void attn_mma(const __half* __restrict__ Qh,
              const __half* __restrict__ Kh, const __half* __restrict__ Vh,
              __half* __restrict__ Oh)
{
    extern __shared__ __align__(1024) char smem[];
    const uint32_t sb = smem_u32(smem);
    const int tid  = threadIdx.x, lane = tid & 31, warp = tid >> 5;
    const int g    = lane >> 2, t4 = lane & 3;
    const int grp  = lane >> 3, wi = lane & 7;
    const int qt   = (int)gridDim.x - 1 - (int)blockIdx.x;
    const int bh   = blockIdx.y, b = bh >> 4, h = bh & 15;
    const size_t bo = (size_t)bh * TT * HD;

    #pragma unroll
    for (int q = 0; q < 4; q++) {
        int idx = q * 128 + tid;
        int row = idx >> 3, ch = idx & 7;
        uint32_t dst = sb + A_QH + row*128 + ((ch ^ (row & 7)) << 4);
        cpa(dst, Qh + bo + (size_t)(qt*64 + row)*HD + ch*8);
    }
    KV_PREFETCH(0, 0); commitg();

    const float LOG2E  = 1.4426950408889634f;
    const float scale2 = 0.125f * LOG2E;
    const float slope2 = exp2f(-0.5f * (float)(h + 1)) * LOG2E;

    float cO[8][4];
    #pragma unroll
    for (int nb = 0; nb < 8; nb++)
        #pragma unroll
        for (int j = 0; j < 4; j++) cO[nb][j] = 0.f;
    float cL[4] = {0.f, 0.f, 0.f, 0.f};   // l via ones-MMA
    uint32_t qfh[4][4];

    const int r0 = qt*64 + warp*16 + g, r1 = r0 + 8;

    for (int kt = 0; kt <= qt; kt++) {
        waitg<0>();
        __syncthreads();
        if (kt < qt) { KV_PREFETCH(kt+1, (kt+1)&1); commitg(); }
        const uint32_t stb = sb + A_ST(kt & 1);

        if (kt == 0) {
            #pragma unroll
            for (int s = 0; s < 4; s++) {
                const int row = warp*16 + (grp & 1)*8 + wi;
                const int cb  = s*32 + (grp >> 1)*16;
                const uint32_t off = row*128 + ((uint32_t)cb ^ (uint32_t)((row & 7) << 4));
                ldsm4(sb + A_QH + off, qfh[s]);
            }
        }

        // ---- S = Q K^T ----
        float cS[8][4];
        #pragma unroll
        for (int nb = 0; nb < 8; nb++)
            #pragma unroll
            for (int j = 0; j < 4; j++) cS[nb][j] = 0.f;

        #pragma unroll
        for (int s = 0; s < 4; s++) {
            #pragma unroll
            for (int nbp = 0; nbp < 4; nbp++) {
                const int row = nbp*16 + (grp >> 1)*8 + wi;
                const int cb  = s*32 + (grp & 1)*16;
                const uint32_t off = row*128 + ((uint32_t)cb ^ (uint32_t)((row & 7) << 4));
                uint32_t kh4[4];
                ldsm4(stb + off, kh4);
                mma_f16(cS[2*nbp],   qfh[s], kh4[0], kh4[1]);
                mma_f16(cS[2*nbp+1], qfh[s], kh4[2], kh4[3]);
            }
        }

        // ---- fixed-shift softmax, fp16x2 exp: p = exp2(scale2*S + slope2*(j-r)) ----
        const bool diag = (kt == qt);
        uint32_t pP[8][2];   // packed fp16 P: [nb][0]=rows r0 pair, [1]=r1 pair
        #pragma unroll
        for (int nb = 0; nb < 8; nb++) {
            const int k0i = kt*64 + nb*8 + t4*2;
            const float d00 = slope2 * (float)(k0i     - r0);
            const float d01 = slope2 * (float)(k0i + 1 - r0);
            const float d10 = slope2 * (float)(k0i     - r1);
            const float d11 = slope2 * (float)(k0i + 1 - r1);
            float v0 = fmaf(cS[nb][0], scale2, d00);
            float v1 = fmaf(cS[nb][1], scale2, d01);
            float v2 = fmaf(cS[nb][2], scale2, d10);
            float v3 = fmaf(cS[nb][3], scale2, d11);
            if (diag) {
                if (k0i     > r0) v0 = -1e30f;
                if (k0i + 1 > r0) v1 = -1e30f;
                if (k0i     > r1) v2 = -1e30f;
                if (k0i + 1 > r1) v3 = -1e30f;
            }
            pP[nb][0] = exp2_h2(pack2h(v0, v1));
            pP[nb][1] = exp2_h2(pack2h(v2, v3));
        }

        // ---- O += P V, l += P @ 1 ----
        #pragma unroll
        for (int s = 0; s < 4; s++) {
            uint32_t aP[4];
            aP[0] = pP[2*s][0];
            aP[1] = pP[2*s][1];
            aP[2] = pP[2*s+1][0];
            aP[3] = pP[2*s+1][1];
            mma_f16(cL, aP, ONES2, ONES2);   // row sums
            #pragma unroll
            for (int nbp = 0; nbp < 4; nbp++) {
                const int row = s*16 + (grp & 1)*8 + wi;
                const int cb  = nbp*32 + (grp >> 1)*16;
                const uint32_t off = row*128 + ((uint32_t)cb ^ (uint32_t)((row & 7) << 4));
                uint32_t vh4[4];
                ldsm4t(stb + 8192 + off, vh4);
                mma_f16(cO[2*nbp],   aP, vh4[0], vh4[1]);
                mma_f16(cO[2*nbp+1], aP, vh4[2], vh4[3]);
            }
        }
    }

    // ---- normalize + write fp16 (cL[0]/cL[2] hold full row sums) ----
    const float i0 = 1.f / cL[0], i1 = 1.f / cL[2];
    const int t0 = qt*64 + warp*16 + g;
    #pragma unroll
    for (int nb = 0; nb < 8; nb++) {
        const int d = h*HD + nb*8 + t4*2;
        const size_t o0 = (size_t)(b*TT + t0) * DD + d;
        const size_t o1 = o0 + (size_t)8 * DD;
        *(__half2*)(Oh + o0) = __floats2half2_rn(cO[nb][0]*i0, cO[nb][1]*i0);
        *(__half2*)(Oh + o1) = __floats2half2_rn(cO[nb][2]*i1, cO[nb][3]*i1);
    }
}

// ---------------------------------------------------------------------------
extern "C" void kernel_launch(void* const* d_in, const int* in_sizes, int n_in,
                              void* d_out, int out_size)
{
    const float* x  = (const float*)d_in[0];
    const float* Wq = (const float*)d_in[1];
    const float* bq = (const float*)d_in[2];
    const float* Wk = (const float*)d_in[3];
    const float* bk = (const float*)d_in[4];
    const float* Wv = (const float*)d_in[5];
    const float* bv = (const float*)d_in[6];
    const float* Wo = (const float*)d_in[7];
    const float* bo = (const float*)d_in[8];
    float* out = (float*)d_out;

    __half *xh,*qh,*kh,*vh,*ah,*wh;
    cudaGetSymbolAddress((void**)&xh, g_xh);
    cudaGetSymbolAddress((void**)&qh, g_qh);
    cudaGetSymbolAddress((void**)&kh, g_kh);
    cudaGetSymbolAddress((void**)&vh, g_vh);
    cudaGetSymbolAddress((void**)&ah, g_ah);
    cudaGetSymbolAddress((void**)&wh, g_wh);

    cudaFuncSetAttribute(mma_gemm<0>, cudaFuncAttributeMaxDynamicSharedMemorySize, GEMM_SMEM);
    cudaFuncSetAttribute(mma_gemm<1>, cudaFuncAttributeMaxDynamicSharedMemorySize, GEMM_SMEM);
    cudaFuncSetAttribute(attn_mma,   cudaFuncAttributeMaxDynamicSharedMemorySize, ATT_SMEM);

    const size_t WSZ = (size_t)DD * DD;

    tohalf<<<(MM*DD/4)/256, 256>>>(x, xh);
    transp4<<<dim3(32, 32, 4), dim3(32, 8)>>>(Wq, Wk, Wv, Wo, wh);

    mma_gemm<1><<<dim3(DD/128, MM/128, 3), 256, GEMM_SMEM>>>(
        xh, wh, bq, bk, bv, nullptr, qh, kh, vh);

    attn_mma<<<dim3(TT/64, BB*HH), 128, ATT_SMEM>>>(qh, kh, vh, ah);

    mma_gemm<0><<<dim3(DD/128, MM/128, 1), 256, GEMM_SMEM>>>(
        ah, wh + 3*WSZ, bo, bo, bo, out, nullptr, nullptr, nullptr);
}